// round 11
// baseline (speedup 1.0000x reference)
#include <cuda_runtime.h>
#include <cuda_fp16.h>
#include <cstdint>
#include <math.h>

// ---------------------------------------------------------------------------
// GRU cell, legacy mma path (tcgen05 rejected by harness PTX target sm_103).
// R11: R6 config (128x128 CTA, 8 warps of 64x32, 256 thr, 2 CTA/SM) with the
// per-stage loads converted from 2048x cp.async(16B) to 256x cp.async.bulk
// (128B rows) + mbarrier complete_tx. Theory: LDGSTS issue rate (rt=8/SMSP)
// was the wall across R5-R10 (tensor%*dur == const; wall/wave == LDGSTS
// issue cycles). Bulk-async cuts load instruction count 8x.
// ---------------------------------------------------------------------------

#define BATCH   16384
#define HID     1024
#define KCAT    2048
#define BK      64            // k halves per stage (4 x k16 MMA steps)
#define NST     3
#define NTH     256

#define BM 128
#define BN 128
#define RS 72                               // smem row stride in halves (144 B)
#define ROW_B 128                           // loaded bytes per row (64 halves)
#define A_STAGE_B (BM * RS * 2)             // 18432 B
#define B_STAGE_B (BN * RS * 2)             // 18432 B
#define STAGE_B   (A_STAGE_B + B_STAGE_B)   // 36864 B
#define SMEM_TOTAL (NST * STAGE_B)          // 110592 B (x2 CTAs <= 228 KB)
#define STAGE_TX  ((BM + BN) * ROW_B)       // 32768 B per stage

// -------------------------- device scratch ---------------------------------
__device__ __half g_A [BATCH * KCAT];
__device__ __half g_Wt[3][HID * KCAT];   // [n][k]
__device__ __half g_rh[BATCH * HID];
__device__ float  g_z [BATCH * HID];
__device__ float  g_hp[BATCH * HID];

// -------------------------- helpers ----------------------------------------
__device__ __forceinline__ void mma_f16(float* c, const uint32_t* a, const uint32_t* b) {
    asm volatile(
        "mma.sync.aligned.m16n8k16.row.col.f32.f16.f16.f32 "
        "{%0,%1,%2,%3}, {%4,%5,%6,%7}, {%8,%9}, {%0,%1,%2,%3};\n"
        : "+f"(c[0]), "+f"(c[1]), "+f"(c[2]), "+f"(c[3])
        : "r"(a[0]), "r"(a[1]), "r"(a[2]), "r"(a[3]),
          "r"(b[0]), "r"(b[1]));
}
__device__ __forceinline__ void ldsm4(uint32_t* r, uint32_t addr) {
    asm volatile("ldmatrix.sync.aligned.m8n8.x4.shared.b16 {%0,%1,%2,%3}, [%4];"
                 : "=r"(r[0]), "=r"(r[1]), "=r"(r[2]), "=r"(r[3]) : "r"(addr));
}
__device__ __forceinline__ uint32_t smem_u32(const void* p) {
    uint32_t a;
    asm("{ .reg .u64 t; cvta.to.shared.u64 t, %1; cvt.u32.u64 %0, t; }" : "=r"(a) : "l"(p));
    return a;
}
__device__ __forceinline__ void mbar_init(uint32_t a, uint32_t cnt) {
    asm volatile("mbarrier.init.shared.b64 [%0], %1;" :: "r"(a), "r"(cnt) : "memory");
}
__device__ __forceinline__ void mbar_expect_tx(uint32_t a, uint32_t bytes) {
    asm volatile("mbarrier.arrive.expect_tx.shared.b64 _, [%0], %1;"
                 :: "r"(a), "r"(bytes) : "memory");
}
__device__ __forceinline__ void mbar_wait(uint32_t a, uint32_t parity) {
    asm volatile(
        "{\n\t.reg .pred P;\n\t"
        "LAB_W_%=:\n\t"
        "mbarrier.try_wait.parity.acquire.cta.shared::cta.b64 P, [%0], %1, 0x989680;\n\t"
        "@P bra.uni LAB_D_%=;\n\t"
        "bra.uni LAB_W_%=;\n\t"
        "LAB_D_%=:\n\t}"
        :: "r"(a), "r"(parity) : "memory");
}
__device__ __forceinline__ void bulk_g2s(uint32_t dst, const void* src, uint32_t bytes,
                                         uint32_t mbar) {
    asm volatile(
        "cp.async.bulk.shared::cta.global.mbarrier::complete_tx::bytes [%0], [%1], %2, [%3];"
        :: "r"(dst), "l"(src), "r"(bytes), "r"(mbar) : "memory");
}
__device__ __forceinline__ void fence_async_shared() {
    asm volatile("fence.proxy.async.shared::cta;" ::: "memory");
}
__device__ __forceinline__ float sigmoidf_fast(float v) { return 1.0f / (1.0f + __expf(-v)); }

// ---------------------------------------------------------------------------
// Prep kernels
// ---------------------------------------------------------------------------
__global__ void prep_concat_kernel(const float* __restrict__ h,
                                   const float* __restrict__ x)
{
    size_t n8 = (size_t)BATCH * KCAT / 8;
    for (size_t i = (size_t)blockIdx.x * blockDim.x + threadIdx.x;
         i < n8; i += (size_t)gridDim.x * blockDim.x) {
        size_t e   = i * 8;
        size_t row = e >> 11;
        size_t col = e & (KCAT - 1);
        const float* src = (col < HID) ? (h + row * HID + col)
                                       : (x + row * HID + (col - HID));
        float4 v0 = ((const float4*)src)[0];
        float4 v1 = ((const float4*)src)[1];
        __half2 o[4];
        o[0] = __float22half2_rn(make_float2(v0.x, v0.y));
        o[1] = __float22half2_rn(make_float2(v0.z, v0.w));
        o[2] = __float22half2_rn(make_float2(v1.x, v1.y));
        o[3] = __float22half2_rn(make_float2(v1.z, v1.w));
        ((uint4*)g_A)[i] = *(uint4*)o;
    }
}

__global__ void prep_weights_kernel(const float* __restrict__ Wr,
                                    const float* __restrict__ Wz,
                                    const float* __restrict__ Wh)
{
    __shared__ float t[32][33];
    const float* src = (blockIdx.z == 0) ? Wr : (blockIdx.z == 1) ? Wz : Wh;
    __half* dst = g_Wt[blockIdx.z];
    int tx = threadIdx.x, ty = threadIdx.y;
    int c0 = blockIdx.x * 32;   // n
    int r0 = blockIdx.y * 32;   // k
    #pragma unroll
    for (int j = 0; j < 32; j += 8)
        t[ty + j][tx] = src[(size_t)(r0 + ty + j) * HID + c0 + tx];
    __syncthreads();
    #pragma unroll
    for (int j = 0; j < 32; j += 8)
        dst[(size_t)(c0 + ty + j) * KCAT + r0 + tx] = __float2half_rn(t[tx][ty + j]);
}

// ---------------------------------------------------------------------------
// Unified GEMM (R6 tile config + bulk-async loads).
// 8 warps: warp_m = wid>>2 (2 x 64 rows), warp_n = wid&3 (4 x 32 cols).
// ---------------------------------------------------------------------------
template <int MODE>
__global__ void __launch_bounds__(NTH, 2)
gru_gemm(const float* __restrict__ h, float* __restrict__ out)
{
    extern __shared__ char smem[];
    __shared__ __align__(8) uint64_t mbar_s[NST];
    const uint32_t sbase = smem_u32(smem);
    const uint32_t mb0   = smem_u32(&mbar_s[0]);
    const int tid    = threadIdx.x;
    const int lane   = tid & 31;
    const int wid    = tid >> 5;
    const int warp_m = wid >> 2;         // 0..1 -> 64-row band
    const int warp_n = wid & 3;          // 0..3 -> 32-col band

    int mat, kstart, KT, col0;
    const __half* Bmat;
    const __half* Amat;
    int astride;
    if (MODE == 1) {
        mat    = blockIdx.x >> 3;        // 0:Wr 1:Wz 2:Wh-bottom
        col0   = (blockIdx.x & 7) * BN;
        kstart = (mat == 2) ? HID : 0;
        KT     = (KCAT - kstart) / BK;   // 32 or 16
        Bmat   = g_Wt[mat];
        Amat   = g_A;  astride = KCAT;
    } else {
        mat    = 0;
        col0   = blockIdx.x * BN;
        kstart = 0;
        KT     = HID / BK;               // 16
        Bmat   = g_Wt[2];
        Amat   = g_rh; astride = HID;
    }
    const int row0 = blockIdx.y * BM;

    if (tid == 0) {
        mbar_init(mb0,      1);
        mbar_init(mb0 + 8,  1);
        mbar_init(mb0 + 16, 1);
    }
    __syncthreads();

    // One 128B bulk row per thread: tid 0..127 -> A rows, 128..255 -> B rows.
    auto issue_stage = [&](int kt) {
        const int slot = kt % NST;
        const uint32_t so = sbase + slot * STAGE_B;
        const uint32_t mb = mb0 + slot * 8;
        const int kbase = kstart + kt * BK;
        if (tid == 0) mbar_expect_tx(mb, STAGE_TX);
        if (tid < BM) {
            bulk_g2s(so + tid * (RS * 2),
                     Amat + (size_t)(row0 + tid) * astride + kbase, ROW_B, mb);
        } else {
            const int r = tid - BM;
            bulk_g2s(so + A_STAGE_B + r * (RS * 2),
                     Bmat + (size_t)(col0 + r) * KCAT + kbase, ROW_B, mb);
        }
    };

    // per-thread ldmatrix base offsets (bytes within stage) — identical to R6
    uint32_t a_off[4];
    #pragma unroll
    for (int mt = 0; mt < 4; mt++)
        a_off[mt] = (warp_m * 64 + mt * 16 + (lane & 15)) * (RS * 2)
                  + ((lane >> 4) & 1) * 16;
    uint32_t b_off[2];
    #pragma unroll
    for (int nt2 = 0; nt2 < 2; nt2++)
        b_off[nt2] = A_STAGE_B
                   + (warp_n * 32 + nt2 * 16 + (lane & 7) + ((lane >> 4) & 1) * 8) * (RS * 2)
                   + ((lane >> 3) & 1) * 16;

    float acc[4][4][4];
    #pragma unroll
    for (int mt = 0; mt < 4; mt++)
        #pragma unroll
        for (int nt = 0; nt < 4; nt++)
            #pragma unroll
            for (int i = 0; i < 4; i++)
                acc[mt][nt][i] = 0.0f;

    issue_stage(0);
    issue_stage(1);

    for (int kt = 0; kt < KT; kt++) {
        __syncthreads();                 // all warps done reading slot (kt-1)%3
        if (kt + 2 < KT) {
            fence_async_shared();        // order prior generic reads vs bulk writes
            issue_stage(kt + 2);
        }
        mbar_wait(mb0 + (kt % NST) * 8, (uint32_t)((kt / NST) & 1));

        const uint32_t so = sbase + (kt % NST) * STAGE_B;
        #pragma unroll
        for (int ks = 0; ks < 4; ks++) {     // four k16 steps per stage
            uint32_t a[4][4], b[2][4];
            #pragma unroll
            for (int mt = 0; mt < 4; mt++)
                ldsm4(a[mt], so + a_off[mt] + ks * 32);
            #pragma unroll
            for (int nt2 = 0; nt2 < 2; nt2++)
                ldsm4(b[nt2], so + b_off[nt2] + ks * 32);
            #pragma unroll
            for (int mt = 0; mt < 4; mt++)
                #pragma unroll
                for (int nt = 0; nt < 4; nt++)
                    mma_f16(acc[mt][nt], a[mt], &b[nt >> 1][(nt & 1) * 2]);
        }
    }

    // ---- epilogue (identical to R6) ----
    #pragma unroll
    for (int mt = 0; mt < 4; mt++) {
        #pragma unroll
        for (int nt = 0; nt < 4; nt++) {
            int r = row0 + warp_m * 64 + mt * 16 + (lane >> 2);
            int c = col0 + warp_n * 32 + nt * 8 + (lane & 3) * 2;
            #pragma unroll
            for (int half_i = 0; half_i < 2; half_i++) {
                int rr = r + half_i * 8;
                size_t gi = (size_t)rr * HID + c;
                float v0 = acc[mt][nt][half_i * 2 + 0];
                float v1 = acc[mt][nt][half_i * 2 + 1];
                if (MODE == 1) {
                    if (mat == 0) {
                        float2 hv = *(const float2*)(h + gi);
                        __half2 o = __float22half2_rn(make_float2(
                            sigmoidf_fast(v0) * hv.x, sigmoidf_fast(v1) * hv.y));
                        *(__half2*)(g_rh + gi) = o;
                    } else if (mat == 1) {
                        float2 o = make_float2(sigmoidf_fast(v0), sigmoidf_fast(v1));
                        *(float2*)(g_z + gi) = o;
                    } else {
                        *(float2*)(g_hp + gi) = make_float2(v0, v1);
                    }
                } else {
                    float2 hp2 = *(const float2*)(g_hp + gi);
                    float2 z2  = *(const float2*)(g_z  + gi);
                    float2 hv2 = *(const float2*)(h    + gi);
                    float t0 = tanhf(v0 + hp2.x);
                    float t1 = tanhf(v1 + hp2.y);
                    float2 o;
                    o.x = hv2.x + z2.x * (t0 - hv2.x);
                    o.y = hv2.y + z2.y * (t1 - hv2.y);
                    *(float2*)(out + gi) = o;
                }
            }
        }
    }
}

// ---------------------------------------------------------------------------

extern "C" void kernel_launch(void* const* d_in, const int* in_sizes, int n_in,
                              void* d_out, int out_size)
{
    const float* h  = (const float*)d_in[0];
    const float* x  = (const float*)d_in[1];
    const float* Wr = (const float*)d_in[2];
    const float* Wz = (const float*)d_in[3];
    const float* Wh = (const float*)d_in[4];
    float* out = (float*)d_out;

    cudaFuncSetAttribute(gru_gemm<1>, cudaFuncAttributeMaxDynamicSharedMemorySize, SMEM_TOTAL);
    cudaFuncSetAttribute(gru_gemm<2>, cudaFuncAttributeMaxDynamicSharedMemorySize, SMEM_TOTAL);

    prep_concat_kernel <<<2048, 256>>>(h, x);
    dim3 gT(HID / 32, KCAT / 32, 3);
    prep_weights_kernel<<<gT, dim3(32, 8)>>>(Wr, Wz, Wh);

    // Phase 1: x-fastest raster -> the 24 column-CTAs of one row panel share A in L2.
    dim3 g1(24, BATCH / BM);
    gru_gemm<1><<<g1, NTH, SMEM_TOTAL>>>(h, out);

    dim3 g2(HID / BN, BATCH / BM);   // (8, 128)
    gru_gemm<2><<<g2, NTH, SMEM_TOTAL>>>(h, out);
}

// round 12
// speedup vs baseline: 1.3074x; 1.3074x over previous
#include <cuda_runtime.h>
#include <cuda_fp16.h>
#include <cstdint>
#include <math.h>

// ---------------------------------------------------------------------------
// GRU cell, legacy mma path (tcgen05 rejected by harness PTX target sm_103).
// R12: exact R6 configuration (best: 695 us) — 128x128 CTA, 8 warps of 64x32,
// 256 thr, 2 CTA/SM, BK=64, NST=3, single barrier/iter, fp16 ldmatrix+mma —
// plus ONE orthogonal change: g_z and g_hp stored as half (saves 128 MB of
// phase-boundary DRAM traffic, entirely outside the mainloop).
// Evidence: R9/R10/R11 falsified fragment-, barrier-domain-, and load-issue-
// theories; the legacy HMMA rate floor doesn't move. Bank the best config.
// ---------------------------------------------------------------------------

#define BATCH   16384
#define HID     1024
#define KCAT    2048
#define BK      64            // k halves per stage (4 x k16 MMA steps)
#define NST     3

#define BM 128
#define BN 128
#define RS 72                               // smem row stride in halves (144 B)
#define A_STAGE_B (BM * RS * 2)             // 18432 B
#define B_STAGE_B (BN * RS * 2)             // 18432 B
#define STAGE_B   (A_STAGE_B + B_STAGE_B)   // 36864 B
#define SMEM_TOTAL (NST * STAGE_B)          // 110592 B

// -------------------------- device scratch ---------------------------------
__device__ __half g_A [BATCH * KCAT];
__device__ __half g_Wt[3][HID * KCAT];   // [n][k]
__device__ __half g_rh[BATCH * HID];
__device__ __half g_z [BATCH * HID];     // half (R12)
__device__ __half g_hp[BATCH * HID];     // half (R12)

// -------------------------- helpers ----------------------------------------
__device__ __forceinline__ void mma_f16(float* c, const uint32_t* a, const uint32_t* b) {
    asm volatile(
        "mma.sync.aligned.m16n8k16.row.col.f32.f16.f16.f32 "
        "{%0,%1,%2,%3}, {%4,%5,%6,%7}, {%8,%9}, {%0,%1,%2,%3};\n"
        : "+f"(c[0]), "+f"(c[1]), "+f"(c[2]), "+f"(c[3])
        : "r"(a[0]), "r"(a[1]), "r"(a[2]), "r"(a[3]),
          "r"(b[0]), "r"(b[1]));
}
__device__ __forceinline__ void ldsm4(uint32_t* r, uint32_t addr) {
    asm volatile("ldmatrix.sync.aligned.m8n8.x4.shared.b16 {%0,%1,%2,%3}, [%4];"
                 : "=r"(r[0]), "=r"(r[1]), "=r"(r[2]), "=r"(r[3]) : "r"(addr));
}
__device__ __forceinline__ void cp16(void* smem_dst, const void* gmem_src) {
    uint32_t s = (uint32_t)__cvta_generic_to_shared(smem_dst);
    asm volatile("cp.async.cg.shared.global [%0], [%1], 16;" :: "r"(s), "l"(gmem_src));
}
__device__ __forceinline__ void cp16u(uint32_t smem_dst, const void* gmem_src) {
    asm volatile("cp.async.cg.shared.global [%0], [%1], 16;" :: "r"(smem_dst), "l"(gmem_src));
}
__device__ __forceinline__ void cp_commit() { asm volatile("cp.async.commit_group;"); }
template <int N>
__device__ __forceinline__ void cp_wait() { asm volatile("cp.async.wait_group %0;" :: "n"(N) : "memory"); }
__device__ __forceinline__ float sigmoidf_fast(float v) { return 1.0f / (1.0f + __expf(-v)); }

// ---------------------------------------------------------------------------
// Prep kernels
// ---------------------------------------------------------------------------
__global__ void prep_concat_kernel(const float* __restrict__ h,
                                   const float* __restrict__ x)
{
    size_t n8 = (size_t)BATCH * KCAT / 8;
    for (size_t i = (size_t)blockIdx.x * blockDim.x + threadIdx.x;
         i < n8; i += (size_t)gridDim.x * blockDim.x) {
        size_t e   = i * 8;
        size_t row = e >> 11;
        size_t col = e & (KCAT - 1);
        const float* src = (col < HID) ? (h + row * HID + col)
                                       : (x + row * HID + (col - HID));
        float4 v0 = ((const float4*)src)[0];
        float4 v1 = ((const float4*)src)[1];
        __half2 o[4];
        o[0] = __float22half2_rn(make_float2(v0.x, v0.y));
        o[1] = __float22half2_rn(make_float2(v0.z, v0.w));
        o[2] = __float22half2_rn(make_float2(v1.x, v1.y));
        o[3] = __float22half2_rn(make_float2(v1.z, v1.w));
        ((uint4*)g_A)[i] = *(uint4*)o;
    }
}

// transpose + convert: g_Wt[g][n][k] = half(W_g[k][n])
__global__ void prep_weights_kernel(const float* __restrict__ Wr,
                                    const float* __restrict__ Wz,
                                    const float* __restrict__ Wh)
{
    __shared__ float t[32][33];
    const float* src = (blockIdx.z == 0) ? Wr : (blockIdx.z == 1) ? Wz : Wh;
    __half* dst = g_Wt[blockIdx.z];
    int tx = threadIdx.x, ty = threadIdx.y;
    int c0 = blockIdx.x * 32;   // n
    int r0 = blockIdx.y * 32;   // k
    #pragma unroll
    for (int j = 0; j < 32; j += 8)
        t[ty + j][tx] = src[(size_t)(r0 + ty + j) * HID + c0 + tx];
    __syncthreads();
    #pragma unroll
    for (int j = 0; j < 32; j += 8)
        dst[(size_t)(c0 + ty + j) * KCAT + r0 + tx] = __float2half_rn(t[tx][ty + j]);
}

// ---------------------------------------------------------------------------
// Unified GEMM (exact R6 mainloop).
// MODE 1: gates (A = g_A).  MODE 2: h-tilde (A = g_rh).
// 8 warps: warp_m = wid>>2 (2 x 64 rows), warp_n = wid&3 (4 x 32 cols).
// ---------------------------------------------------------------------------
template <int MODE>
__global__ void __launch_bounds__(256, 2)
gru_gemm(const float* __restrict__ h, float* __restrict__ out)
{
    extern __shared__ char smem[];
    const uint32_t sbase = (uint32_t)__cvta_generic_to_shared(smem);
    const int tid    = threadIdx.x;
    const int lane   = tid & 31;
    const int wid    = tid >> 5;
    const int warp_m = wid >> 2;         // 0..1 -> 64-row band
    const int warp_n = wid & 3;          // 0..3 -> 32-col band

    int mat, kstart, KT, col0;
    const __half* Bmat;
    const __half* Amat;
    int astride;
    if (MODE == 1) {
        mat    = blockIdx.x >> 3;        // 0:Wr 1:Wz 2:Wh-bottom
        col0   = (blockIdx.x & 7) * BN;
        kstart = (mat == 2) ? HID : 0;
        KT     = (KCAT - kstart) / BK;   // 32 or 16
        Bmat   = g_Wt[mat];
        Amat   = g_A;  astride = KCAT;
    } else {
        mat    = 0;
        col0   = blockIdx.x * BN;
        kstart = 0;
        KT     = HID / BK;               // 16
        Bmat   = g_Wt[2];
        Amat   = g_rh; astride = HID;
    }
    const int row0 = blockIdx.y * BM;

    auto load_stage = [&](int kt) {
        const uint32_t so = sbase + (kt % NST) * STAGE_B;
        const int kbase = kstart + kt * BK;
        #pragma unroll
        for (int j = 0; j < 4; j++) {        // A: 128 rows x 8 16B-chunks
            int idx = tid + j * 256;
            int r = idx >> 3, c = idx & 7;
            cp16u(so + r * (RS * 2) + c * 16,
                  Amat + (size_t)(row0 + r) * astride + kbase + c * 8);
        }
        #pragma unroll
        for (int j = 0; j < 4; j++) {        // B: 128 n-rows x 8 chunks
            int idx = tid + j * 256;
            int r = idx >> 3, c = idx & 7;
            cp16u(so + A_STAGE_B + r * (RS * 2) + c * 16,
                  Bmat + (size_t)(col0 + r) * KCAT + kbase + c * 8);
        }
        cp_commit();
    };

    // per-thread ldmatrix base offsets (bytes within stage)
    uint32_t a_off[4];
    #pragma unroll
    for (int mt = 0; mt < 4; mt++)
        a_off[mt] = (warp_m * 64 + mt * 16 + (lane & 15)) * (RS * 2)
                  + ((lane >> 4) & 1) * 16;
    uint32_t b_off[2];
    #pragma unroll
    for (int nt2 = 0; nt2 < 2; nt2++)
        b_off[nt2] = A_STAGE_B
                   + (warp_n * 32 + nt2 * 16 + (lane & 7) + ((lane >> 4) & 1) * 8) * (RS * 2)
                   + ((lane >> 3) & 1) * 16;

    float acc[4][4][4];
    #pragma unroll
    for (int mt = 0; mt < 4; mt++)
        #pragma unroll
        for (int nt = 0; nt < 4; nt++)
            #pragma unroll
            for (int i = 0; i < 4; i++)
                acc[mt][nt][i] = 0.0f;

    load_stage(0);
    load_stage(1);

    for (int kt = 0; kt < KT; kt++) {
        if (kt < KT - 1) cp_wait<1>(); else cp_wait<0>();
        __syncthreads();                 // single barrier per iteration
        if (kt + 2 < KT) load_stage(kt + 2);

        const uint32_t so = sbase + (kt % NST) * STAGE_B;
        #pragma unroll
        for (int ks = 0; ks < 4; ks++) {     // four k16 steps per stage
            uint32_t a[4][4], b[2][4];
            #pragma unroll
            for (int mt = 0; mt < 4; mt++)
                ldsm4(a[mt], so + a_off[mt] + ks * 32);
            #pragma unroll
            for (int nt2 = 0; nt2 < 2; nt2++)
                ldsm4(b[nt2], so + b_off[nt2] + ks * 32);
            #pragma unroll
            for (int mt = 0; mt < 4; mt++)
                #pragma unroll
                for (int nt = 0; nt < 4; nt++)
                    mma_f16(acc[mt][nt], a[mt], &b[nt >> 1][(nt & 1) * 2]);
        }
        // no trailing barrier: 3-deep ring, next write to this stage is gated
        // by the next top-of-loop barrier.
    }

    // ---- epilogue ----
    #pragma unroll
    for (int mt = 0; mt < 4; mt++) {
        #pragma unroll
        for (int nt = 0; nt < 4; nt++) {
            int r = row0 + warp_m * 64 + mt * 16 + (lane >> 2);
            int c = col0 + warp_n * 32 + nt * 8 + (lane & 3) * 2;
            #pragma unroll
            for (int half_i = 0; half_i < 2; half_i++) {
                int rr = r + half_i * 8;
                size_t gi = (size_t)rr * HID + c;
                float v0 = acc[mt][nt][half_i * 2 + 0];
                float v1 = acc[mt][nt][half_i * 2 + 1];
                if (MODE == 1) {
                    if (mat == 0) {
                        float2 hv = *(const float2*)(h + gi);
                        __half2 o = __float22half2_rn(make_float2(
                            sigmoidf_fast(v0) * hv.x, sigmoidf_fast(v1) * hv.y));
                        *(__half2*)(g_rh + gi) = o;
                    } else if (mat == 1) {
                        __half2 o = __float22half2_rn(make_float2(
                            sigmoidf_fast(v0), sigmoidf_fast(v1)));
                        *(__half2*)(g_z + gi) = o;
                    } else {
                        *(__half2*)(g_hp + gi) = __float22half2_rn(make_float2(v0, v1));
                    }
                } else {
                    float2 hp2 = __half22float2(*(const __half2*)(g_hp + gi));
                    float2 z2  = __half22float2(*(const __half2*)(g_z  + gi));
                    float2 hv2 = *(const float2*)(h + gi);
                    float t0 = tanhf(v0 + hp2.x);
                    float t1 = tanhf(v1 + hp2.y);
                    float2 o;
                    o.x = hv2.x + z2.x * (t0 - hv2.x);
                    o.y = hv2.y + z2.y * (t1 - hv2.y);
                    *(float2*)(out + gi) = o;
                }
            }
        }
    }
}

// ---------------------------------------------------------------------------

extern "C" void kernel_launch(void* const* d_in, const int* in_sizes, int n_in,
                              void* d_out, int out_size)
{
    const float* h  = (const float*)d_in[0];
    const float* x  = (const float*)d_in[1];
    const float* Wr = (const float*)d_in[2];
    const float* Wz = (const float*)d_in[3];
    const float* Wh = (const float*)d_in[4];
    float* out = (float*)d_out;

    cudaFuncSetAttribute(gru_gemm<1>, cudaFuncAttributeMaxDynamicSharedMemorySize, SMEM_TOTAL);
    cudaFuncSetAttribute(gru_gemm<2>, cudaFuncAttributeMaxDynamicSharedMemorySize, SMEM_TOTAL);

    prep_concat_kernel <<<2048, 256>>>(h, x);
    dim3 gT(HID / 32, KCAT / 32, 3);
    prep_weights_kernel<<<gT, dim3(32, 8)>>>(Wr, Wz, Wh);

    // Phase 1: x-fastest raster -> the 24 column-CTAs of one row panel share A in L2.
    dim3 g1(24, BATCH / BM);
    gru_gemm<1><<<g1, 256, SMEM_TOTAL>>>(h, out);

    dim3 g2(HID / BN, BATCH / BM);   // (8, 128)
    gru_gemm<2><<<g2, 256, SMEM_TOTAL>>>(h, out);
}